// round 2
// baseline (speedup 1.0000x reference)
#include <cuda_runtime.h>

// CosmosUnpatcher3d: one Haar IDWT level (2,24,9,256,256) -> slice -> (2,3,17,512,512).
// Combined tap c^3*sqrt(8) = 1 exactly: each 2x2x2 output block is the 8-point
// Walsh-Hadamard transform of the 8 band values at that (t,h,w).
//
// R2: one thread per input float4 (4 w columns) per (b,ch,t,h).
//  - 8x LDG.128 streaming loads (__ldcs), fully coalesced, MLP=8 @ 16B each
//  - WHT factorized per parity axis inside the pt loop (short live ranges)
//  - per (pt,ph): 2x STG.128 streaming stores (__stcs), 1KB contiguous per warp

#define BAND_STRIDE4 (3 * 9 * 256 * 64)   // band stride in float4 units (442368)

__global__ __launch_bounds__(256)
void idwt_haar_kernel(const float4* __restrict__ in, float* __restrict__ out) {
    int tid = blockIdx.x * 256 + threadIdx.x;
    // total threads = 2*3*9*256*64 = 884,736 (exact grid)
    int wq = tid & 63;           // w-quad index [0,64)
    int h  = (tid >> 6) & 255;   // input h [0,256)
    int r  = tid >> 14;          // [0,54) = (b*3+ch)*9 + t
    int t  = r % 9;
    int bc = r / 9;              // b*3 + ch
    int b  = bc / 3;
    int ch = bc - 3 * b;

    // input float4 index: (((b*24 + band*3 + ch)*9 + t)*256 + h)*64 + wq
    int ibase = (((b * 24 + ch) * 9 + t) * 256 + h) * 64 + wq;

    float v[8][4];
#pragma unroll
    for (int s = 0; s < 8; s++) {
        float4 q = __ldcs(in + ibase + s * BAND_STRIDE4);
        v[s][0] = q.x; v[s][1] = q.y; v[s][2] = q.z; v[s][3] = q.w;
    }

    // band = bt*4 + bh*2 + bw ; out parity p = pt*4 + ph*2 + pw
    // out[p] = sum_band prod_axes (-1)^(band_bit & p_bit)  — factorized below.
#pragma unroll
    for (int pt = 0; pt < 2; pt++) {
        int t2 = 2 * t + pt - 1;   // output T index after [:,:,1:] slice
        if (t2 < 0) continue;

        float u[4][4];             // t-axis combine: u[bh*2+bw][col]
#pragma unroll
        for (int j = 0; j < 4; j++)
#pragma unroll
            for (int k = 0; k < 4; k++)
                u[j][k] = pt == 0 ? (v[j][k] + v[4 + j][k])
                                  : (v[j][k] - v[4 + j][k]);

#pragma unroll
        for (int ph = 0; ph < 2; ph++) {
            float w0[4], w1[4];    // h-axis combine: w{bw}[col]
#pragma unroll
            for (int k = 0; k < 4; k++) {
                w0[k] = ph == 0 ? (u[0][k] + u[2][k]) : (u[0][k] - u[2][k]);
                w1[k] = ph == 0 ? (u[1][k] + u[3][k]) : (u[1][k] - u[3][k]);
            }
            // w-axis combine + store: out w = 8*wq + 2*col + pw
            int obase = ((bc * 17 + t2) << 18) + (((h << 1) + ph) << 9) + (wq << 3);
            float4 lo = make_float4(w0[0] + w1[0], w0[0] - w1[0],
                                    w0[1] + w1[1], w0[1] - w1[1]);
            float4 hi = make_float4(w0[2] + w1[2], w0[2] - w1[2],
                                    w0[3] + w1[3], w0[3] - w1[3]);
            __stcs((float4*)(out + obase), lo);
            __stcs((float4*)(out + obase + 4), hi);
        }
    }
}

extern "C" void kernel_launch(void* const* d_in, const int* in_sizes, int n_in,
                              void* d_out, int out_size) {
    const float4* in = (const float4*)d_in[0];
    float* out = (float*)d_out;
    // 884,736 threads / 256 = 3456 blocks
    idwt_haar_kernel<<<3456, 256>>>(in, out);
}

// round 3
// speedup vs baseline: 1.0389x; 1.0389x over previous
#include <cuda_runtime.h>

// CosmosUnpatcher3d: one Haar IDWT level (2,24,9,256,256) -> slice -> (2,3,17,512,512).
// Combined tap c^3*sqrt(8) = 1 exactly: each 2x2x2 output block is the 8-point
// Walsh-Hadamard transform of the 8 band values at that (t,h,w).
//
// R3 = R1 structure (float2 loads, 32 regs, high occupancy) + streaming cache
// hints (__ldcs/__stcs; both arrays touched exactly once) + leaner indexing.

#define BAND_STRIDE2 (3 * 9 * 256 * 128)   // band stride in float2 units

__device__ __forceinline__ void wht8(const float v0, const float v1, const float v2,
                                     const float v3, const float v4, const float v5,
                                     const float v6, const float v7, float o[8]) {
    float a0 = v0 + v1, a1 = v0 - v1;
    float a2 = v2 + v3, a3 = v2 - v3;
    float a4 = v4 + v5, a5 = v4 - v5;
    float a6 = v6 + v7, a7 = v6 - v7;
    float b0 = a0 + a2, b2 = a0 - a2;
    float b1 = a1 + a3, b3 = a1 - a3;
    float b4 = a4 + a6, b6 = a4 - a6;
    float b5 = a5 + a7, b7 = a5 - a7;
    o[0] = b0 + b4; o[4] = b0 - b4;
    o[1] = b1 + b5; o[5] = b1 - b5;
    o[2] = b2 + b6; o[6] = b2 - b6;
    o[3] = b3 + b7; o[7] = b3 - b7;
}

__global__ __launch_bounds__(256)
void idwt_haar_kernel(const float2* __restrict__ in, float* __restrict__ out) {
    int tid = blockIdx.x * 256 + threadIdx.x;
    // total threads = 2*3*9*256*128 = 1,769,472 (exact grid)
    int wp  = tid & 127;          // w-pair index [0,128)
    int h   = (tid >> 7) & 255;   // input h [0,256)
    int r   = tid >> 15;          // [0,54) = (b*3+ch)*9 + t
    int bc  = r / 9;              // b*3 + ch
    int t   = r - bc * 9;
    int b   = bc / 3;
    int ch  = bc - 3 * b;

    // input base in float2 units: (((b*24+ch)*9+t)*256 + h)*128 + wp
    int ibase = ((((b * 24 + ch) * 9 + t) << 8) + h) * 128 + wp;

    float2 v0 = __ldcs(in + ibase + 0 * BAND_STRIDE2);
    float2 v1 = __ldcs(in + ibase + 1 * BAND_STRIDE2);
    float2 v2 = __ldcs(in + ibase + 2 * BAND_STRIDE2);
    float2 v3 = __ldcs(in + ibase + 3 * BAND_STRIDE2);
    float2 v4 = __ldcs(in + ibase + 4 * BAND_STRIDE2);
    float2 v5 = __ldcs(in + ibase + 5 * BAND_STRIDE2);
    float2 v6 = __ldcs(in + ibase + 6 * BAND_STRIDE2);
    float2 v7 = __ldcs(in + ibase + 7 * BAND_STRIDE2);

    float x[8], y[8];
    wht8(v0.x, v1.x, v2.x, v3.x, v4.x, v5.x, v6.x, v7.x, x);
    wht8(v0.y, v1.y, v2.y, v3.y, v4.y, v5.y, v6.y, v7.y, y);

    // Output (2,3,17,512,512): t2 = 2t + pt - 1 (drop t2 < 0).
#pragma unroll
    for (int pt = 0; pt < 2; pt++) {
        int t2 = 2 * t + pt - 1;
        if (t2 < 0) continue;
#pragma unroll
        for (int ph = 0; ph < 2; ph++) {
            int p = pt * 4 + ph * 2;
            int obase = ((bc * 17 + t2) << 18) + (((h << 1) + ph) << 9) + (wp << 2);
            __stcs((float4*)(out + obase),
                   make_float4(x[p], x[p + 1], y[p], y[p + 1]));
        }
    }
}

extern "C" void kernel_launch(void* const* d_in, const int* in_sizes, int n_in,
                              void* d_out, int out_size) {
    const float2* in = (const float2*)d_in[0];
    float* out = (float*)d_out;
    idwt_haar_kernel<<<6912, 256>>>(in, out);
}

// round 4
// speedup vs baseline: 1.0459x; 1.0068x over previous
#include <cuda_runtime.h>

// CosmosUnpatcher3d: one Haar IDWT level (2,24,9,256,256) -> slice -> (2,3,17,512,512).
// Combined tap c^3*sqrt(8) = 1 exactly: each 2x2x2 output block is the 8-point
// Walsh-Hadamard transform of the 8 band values at that (t,h,w).
//
// R4 = R1 structure (float2 loads, 32 regs, ~79% occ) with:
//  - __ldcg loads  : L2-only, no L1 allocate (read-once stream)
//  - default stores: write-allocate in L2, lazy batched writeback to DRAM
//    (reduces HBM read/write turnaround vs eager .cs drain — R3 evidence)

#define BAND_STRIDE2 (3 * 9 * 256 * 128)   // band stride in float2 units

__device__ __forceinline__ void wht8(const float v0, const float v1, const float v2,
                                     const float v3, const float v4, const float v5,
                                     const float v6, const float v7, float o[8]) {
    float a0 = v0 + v1, a1 = v0 - v1;
    float a2 = v2 + v3, a3 = v2 - v3;
    float a4 = v4 + v5, a5 = v4 - v5;
    float a6 = v6 + v7, a7 = v6 - v7;
    float b0 = a0 + a2, b2 = a0 - a2;
    float b1 = a1 + a3, b3 = a1 - a3;
    float b4 = a4 + a6, b6 = a4 - a6;
    float b5 = a5 + a7, b7 = a5 - a7;
    o[0] = b0 + b4; o[4] = b0 - b4;
    o[1] = b1 + b5; o[5] = b1 - b5;
    o[2] = b2 + b6; o[6] = b2 - b6;
    o[3] = b3 + b7; o[7] = b3 - b7;
}

__global__ __launch_bounds__(256)
void idwt_haar_kernel(const float2* __restrict__ in, float* __restrict__ out) {
    int tid = blockIdx.x * 256 + threadIdx.x;
    // total threads = 2*3*9*256*128 = 1,769,472 (exact grid)
    int wp  = tid & 127;          // w-pair index [0,128)
    int h   = (tid >> 7) & 255;   // input h [0,256)
    int r   = tid >> 15;          // [0,54) = (b*3+ch)*9 + t
    int bc  = r / 9;              // b*3 + ch
    int t   = r - bc * 9;
    int b   = bc / 3;
    int ch  = bc - 3 * b;

    // input base in float2 units: (((b*24+ch)*9+t)*256 + h)*128 + wp
    int ibase = ((((b * 24 + ch) * 9 + t) << 8) + h) * 128 + wp;

    float2 v0 = __ldcg(in + ibase + 0 * BAND_STRIDE2);
    float2 v1 = __ldcg(in + ibase + 1 * BAND_STRIDE2);
    float2 v2 = __ldcg(in + ibase + 2 * BAND_STRIDE2);
    float2 v3 = __ldcg(in + ibase + 3 * BAND_STRIDE2);
    float2 v4 = __ldcg(in + ibase + 4 * BAND_STRIDE2);
    float2 v5 = __ldcg(in + ibase + 5 * BAND_STRIDE2);
    float2 v6 = __ldcg(in + ibase + 6 * BAND_STRIDE2);
    float2 v7 = __ldcg(in + ibase + 7 * BAND_STRIDE2);

    float x[8], y[8];
    wht8(v0.x, v1.x, v2.x, v3.x, v4.x, v5.x, v6.x, v7.x, x);
    wht8(v0.y, v1.y, v2.y, v3.y, v4.y, v5.y, v6.y, v7.y, y);

    // Output (2,3,17,512,512): t2 = 2t + pt - 1 (drop t2 < 0).
#pragma unroll
    for (int pt = 0; pt < 2; pt++) {
        int t2 = 2 * t + pt - 1;
        if (t2 < 0) continue;
#pragma unroll
        for (int ph = 0; ph < 2; ph++) {
            int p = pt * 4 + ph * 2;
            int obase = ((bc * 17 + t2) << 18) + (((h << 1) + ph) << 9) + (wp << 2);
            *(float4*)(out + obase) = make_float4(x[p], x[p + 1], y[p], y[p + 1]);
        }
    }
}

extern "C" void kernel_launch(void* const* d_in, const int* in_sizes, int n_in,
                              void* d_out, int out_size) {
    const float2* in = (const float2*)d_in[0];
    float* out = (float*)d_out;
    idwt_haar_kernel<<<6912, 256>>>(in, out);
}